// round 2
// baseline (speedup 1.0000x reference)
#include <cuda_runtime.h>
#include <cuda_bf16.h>

// VideoEmbedding: out[n, d] = sum_k W[vid[n], d, k] * basis(t[n])[k]
// basis = [1, sin(2^j*pi*t) j=0..5, cos(2^j*pi*t) j=0..5], K = 13, D = 32, V = 32.
//
// Round 1 (baseline re-submit; prior rounds failed on infra):
//  - prolog kernel transposes weights [V,D,K] -> [V,K,D] into a __device__
//    scratch so the hot loop reads aligned float4 rows (d contiguous, 128B rows).
//  - main kernel: 1 thread = 1 ray. sincospif + double-angle recurrence for the
//    basis, 13x8 float4 FMA accumulation (weights live in L1: 53KB total),
//    8x STG.128 output.

#define EMB_V 32
#define EMB_D 32
#define EMB_F 6
#define EMB_K (2 * EMB_F + 1)   // 13

// Transposed weights scratch: [V][K][D] floats = 32*13*32 = 13312 floats.
__device__ float g_wt[EMB_V * EMB_K * EMB_D];

__global__ void transpose_weights_kernel(const float* __restrict__ w) {
    int i = blockIdx.x * blockDim.x + threadIdx.x;
    const int total = EMB_V * EMB_K * EMB_D;
    if (i >= total) return;
    int v = i / (EMB_K * EMB_D);
    int r = i - v * (EMB_K * EMB_D);
    int k = r / EMB_D;
    int d = r - k * EMB_D;
    // source layout: [V][D][K]
    g_wt[i] = w[v * (EMB_D * EMB_K) + d * EMB_K + k];
}

__global__ void __launch_bounds__(512)
video_embedding_kernel(const float* __restrict__ times,
                       const int* __restrict__ vids,
                       float* __restrict__ out,
                       int n) {
    int i = blockIdx.x * blockDim.x + threadIdx.x;
    if (i >= n) return;

    float t = __ldg(times + i);
    int v = __ldg(vids + i);

    // Fourier basis via sincospi + double-angle recurrence.
    // b[0]=1, b[1+j]=sin(2^j*pi*t), b[7+j]=cos(2^j*pi*t)
    float b[EMB_K];
    b[0] = 1.0f;
    float s, c;
    sincospif(t, &s, &c);
#pragma unroll
    for (int j = 0; j < EMB_F; j++) {
        b[1 + j] = s;
        b[1 + EMB_F + j] = c;
        float s2 = 2.0f * s * c;
        float c2 = fmaf(c, c, -s * s);  // cos(2x) = c^2 - s^2
        s = s2;
        c = c2;
    }

    const float4* wp = reinterpret_cast<const float4*>(g_wt) + (size_t)v * (EMB_K * (EMB_D / 4));

    float4 acc[EMB_D / 4];
#pragma unroll
    for (int j = 0; j < EMB_D / 4; j++) acc[j] = make_float4(0.f, 0.f, 0.f, 0.f);

#pragma unroll
    for (int k = 0; k < EMB_K; k++) {
        float bk = b[k];
#pragma unroll
        for (int j = 0; j < EMB_D / 4; j++) {
            float4 w4 = wp[k * (EMB_D / 4) + j];
            acc[j].x = fmaf(bk, w4.x, acc[j].x);
            acc[j].y = fmaf(bk, w4.y, acc[j].y);
            acc[j].z = fmaf(bk, w4.z, acc[j].z);
            acc[j].w = fmaf(bk, w4.w, acc[j].w);
        }
    }

    float4* op = reinterpret_cast<float4*>(out) + (size_t)i * (EMB_D / 4);
#pragma unroll
    for (int j = 0; j < EMB_D / 4; j++) op[j] = acc[j];
}

extern "C" void kernel_launch(void* const* d_in, const int* in_sizes, int n_in,
                              void* d_out, int out_size) {
    const float* times = (const float*)d_in[0];
    const int* vids = (const int*)d_in[1];
    const float* weights = (const float*)d_in[2];
    float* out = (float*)d_out;

    int n = in_sizes[0];  // times is [N, 1]

    // Prolog: transpose weights into [V][K][D] scratch.
    const int total_w = EMB_V * EMB_K * EMB_D;
    transpose_weights_kernel<<<(total_w + 255) / 256, 256>>>(weights);

    // Main kernel: one thread per ray.
    video_embedding_kernel<<<(n + 511) / 512, 512>>>(times, vids, out, n);
}

// round 4
// speedup vs baseline: 4.0617x; 4.0617x over previous
#include <cuda_runtime.h>
#include <cuda_bf16.h>

// VideoEmbedding: out[n, d] = sum_k W[vid[n], d, k] * basis(t[n])[k]
// K = 13, D = 32, V = 32, N = 1048576.
//
// Round 3 (resubmit of round-2 design; infra timeout ate the bench):
//  - weights in SMEM, layout [K][D][V]: scalar LDS at bank = vid -> conflict-free
//    (distinct vids = distinct banks, duplicates = broadcast). 1664 B/ray at the
//    128 B/cyc crossbar rate instead of ~20 line-replays per LDG.
//  - stores: warp-private XOR-swizzled 4KB smem slice to transpose 32 rows, then
//    each STG.128 writes 4 COMPLETE 128B output rows (was: 16B partial writes to
//    32 lines per instruction = 8x wavefront inflation).

#define EMB_V 32
#define EMB_D 32
#define EMB_F 6
#define EMB_K (2 * EMB_F + 1)   // 13
#define SW_FLOATS (EMB_K * EMB_D * EMB_V)  // 13312 floats = 52KB
#define THREADS 256
#define WARPS (THREADS / 32)

// Weights transposed to [K][D][V] so smem bank of W[k][d][v] == v.
__device__ float g_wt[SW_FLOATS];

__global__ void transpose_weights_kernel(const float* __restrict__ w) {
    int i = blockIdx.x * blockDim.x + threadIdx.x;
    if (i >= SW_FLOATS) return;
    // destination index i = (k*32 + d)*32 + v
    int v = i & 31;
    int kd = i >> 5;
    int d = kd & 31;
    int k = kd >> 5;
    g_wt[i] = w[v * (EMB_D * EMB_K) + d * EMB_K + k];
}

__global__ void __launch_bounds__(THREADS)
video_embedding_kernel(const float* __restrict__ times,
                       const int* __restrict__ vids,
                       float* __restrict__ out,
                       int n) {
    extern __shared__ float smem[];
    float* sw = smem;                                   // [13][32][32] floats, 52KB
    float4* slice = reinterpret_cast<float4*>(smem + SW_FLOATS);  // [WARPS][32][8], 32KB

    int tid = threadIdx.x;

    // Cooperative copy of weights into smem (linear float4, conflict-free).
    {
        const float4* gw4 = reinterpret_cast<const float4*>(g_wt);
        float4* sw4 = reinterpret_cast<float4*>(sw);
#pragma unroll
        for (int i = 0; i < SW_FLOATS / 4 / THREADS; i++)
            sw4[tid + i * THREADS] = gw4[tid + i * THREADS];
    }
    __syncthreads();

    int lane = tid & 31;
    int wid = tid >> 5;
    int warp_base = blockIdx.x * THREADS + wid * 32;   // first ray of this warp
    int ray = warp_base + lane;
    bool valid = (ray < n);

    float acc[EMB_D];
#pragma unroll
    for (int d = 0; d < EMB_D; d++) acc[d] = 0.0f;

    if (valid) {
        float t = __ldg(times + ray);
        int v = __ldg(vids + ray);

        // Fourier basis: b[0]=1, b[1+j]=sin(2^j pi t), b[7+j]=cos(2^j pi t)
        float b[EMB_K];
        b[0] = 1.0f;
        float s, c;
        sincospif(t, &s, &c);
#pragma unroll
        for (int j = 0; j < EMB_F; j++) {
            b[1 + j] = s;
            b[1 + EMB_F + j] = c;
            float s2 = 2.0f * s * c;
            float c2 = fmaf(c, c, -s * s);
            s = s2;
            c = c2;
        }

        const float* swb = sw + v;   // bank v for this thread
#pragma unroll
        for (int k = 0; k < EMB_K; k++) {
            float bk = b[k];
#pragma unroll
            for (int d = 0; d < EMB_D; d++) {
                acc[d] = fmaf(bk, swb[(k * EMB_D + d) * EMB_V], acc[d]);
            }
        }
    }

    // Store. Fast path: whole warp in range -> transpose via swizzled slice,
    // then STG.128 writing 4 complete 128B rows per instruction.
    // (128-bit smem ops run in quarter-warp phases of 8 lanes; both the write
    //  pattern idx%8 = j^(lane&7) and the read pattern idx%8 = q^(r&7) give 8
    //  distinct bank-groups per phase -> conflict-free.)
    float4* sl = slice + wid * 32 * 8;
    if (warp_base + 32 <= n) {
#pragma unroll
        for (int j = 0; j < 8; j++) {
            sl[lane * 8 + (j ^ (lane & 7))] =
                make_float4(acc[4 * j], acc[4 * j + 1], acc[4 * j + 2], acc[4 * j + 3]);
        }
        __syncwarp();
        float4* ob = reinterpret_cast<float4*>(out) + (size_t)warp_base * 8;
#pragma unroll
        for (int m = 0; m < 8; m++) {
            int r = 4 * m + (lane >> 3);   // row within warp
            int q = lane & 7;              // float4 index within row
            float4 val = sl[r * 8 + (q ^ (r & 7))];
            ob[(size_t)r * 8 + q] = val;
        }
    } else if (valid) {
        // Tail fallback: direct (slow) per-thread row store.
        float4* op = reinterpret_cast<float4*>(out) + (size_t)ray * 8;
#pragma unroll
        for (int j = 0; j < 8; j++)
            op[j] = make_float4(acc[4 * j], acc[4 * j + 1], acc[4 * j + 2], acc[4 * j + 3]);
    }
}

extern "C" void kernel_launch(void* const* d_in, const int* in_sizes, int n_in,
                              void* d_out, int out_size) {
    const float* times = (const float*)d_in[0];
    const int* vids = (const int*)d_in[1];
    const float* weights = (const float*)d_in[2];
    float* out = (float*)d_out;

    int n = in_sizes[0];

    size_t dyn_smem = (size_t)(SW_FLOATS + WARPS * 32 * 8 * 4) * 4;
    cudaFuncSetAttribute(video_embedding_kernel,
                         cudaFuncAttributeMaxDynamicSharedMemorySize,
                         (int)dyn_smem);

    transpose_weights_kernel<<<(SW_FLOATS + 255) / 256, 256>>>(weights);

    int blocks = (n + THREADS - 1) / THREADS;
    video_embedding_kernel<<<blocks, THREADS, dyn_smem>>>(times, vids, out, n);
}